// round 3
// baseline (speedup 1.0000x reference)
#include <cuda_runtime.h>
#include <cuda_bf16.h>

// Problem constants
#define TT 128
#define BB 64
#define HH 128
#define EE0 128
#define MM (TT*BB)   // 8192 rows

// ---------------- scratch (static device globals; no allocation) -------------
__device__ float g_ms [MM*HH];     // running mean  [T,B,H]
__device__ float g_x1 [MM*HH];     // inputs@w1 + b [T,B,H]
__device__ float g_q  [MM*HH];     // x2 + wms      [T,B,H]
__device__ float g_sc [BB*TT*TT];  // scores        [B,Ti,Tj]
__device__ float g_ma [MM*HH];     // attended mean [T,B,H]
__device__ float g_a0c[MM*EE0];
__device__ float g_b0c[MM*EE0];
__device__ float g_a0v[MM*EE0];
__device__ float g_b0v[MM*EE0];

// ---------------- helpers ----------------------------------------------------
__device__ __forceinline__ float sigf(float x) {
    // 1/(1+e^-x): EX2 + RCP MUFU path, rel err ~2^-21
    return __fdividef(1.0f, 1.0f + __expf(-x));
}
__device__ __forceinline__ float leaky(float v) {
    return (v >= 0.0f) ? v : 0.3f * v;
}

// ---------------- kernel 1: running mean over time prefix --------------------
__global__ void cumsum_k(const float* __restrict__ in) {
    int c = blockIdx.x * 256 + threadIdx.x;   // column over (b,h): 8192
    if (c >= BB*HH) return;
    float run = 0.0f;
    #pragma unroll 4
    for (int i = 0; i < TT; i++) {
        run += in[i*BB*HH + c];
        g_ms[i*BB*HH + c] = run / (float)(i + 1);
    }
}

// ---------------- big GEMM: out = act(A@W + bias [+ A2@W2]) ------------------
// A row-major [8192 x 128], W row-major [128 x 128]. BM=128, BK=16, 256 thr.
// 8x8 per-thread register tile; all smem traffic is LDS.128/STS-friendly.
struct GJob { const float* A; const float* W; const float* bias;
              const float* A2; const float* W2; float* out; };
struct GJobs { GJob j[4]; };

template<int ACT>
__global__ __launch_bounds__(256)
void gemm128_k(GJobs jobs)
{
    constexpr int BM = 128, BK = 16, K = 128, N = 128;
    __shared__ float As[2][BK][BM + 4];   // [k][row], +4 pad keeps 16B align
    __shared__ float Ws[2][BK][N];

    const GJob jb = jobs.j[blockIdx.y];
    const bool dual = (jb.A2 != nullptr);
    const int tid = threadIdx.x;
    const int tx = tid & 15;              // cols tx*8 .. tx*8+7
    const int ty = tid >> 4;              // rows ty*8 .. ty*8+7
    const int row0 = blockIdx.x * BM;

    float acc[8][8];
    #pragma unroll
    for (int j = 0; j < 8; j++)
        #pragma unroll
        for (int c = 0; c < 8; c++) acc[j][c] = 0.0f;

    for (int k0 = 0; k0 < K; k0 += BK) {
        // A tile(s): 128 rows x 16 k = 512 float4, 2 per thread
        #pragma unroll
        for (int l = 0; l < 2; l++) {
            int e = tid + l*256;
            int kq = e & 3, r = e >> 2;           // kq: float4 group in k
            float4 v = *(const float4*)(jb.A + (size_t)(row0 + r)*K + k0 + kq*4);
            As[0][kq*4+0][r] = v.x; As[0][kq*4+1][r] = v.y;
            As[0][kq*4+2][r] = v.z; As[0][kq*4+3][r] = v.w;
            if (dual) {
                float4 u = *(const float4*)(jb.A2 + (size_t)(row0 + r)*K + k0 + kq*4);
                As[1][kq*4+0][r] = u.x; As[1][kq*4+1][r] = u.y;
                As[1][kq*4+2][r] = u.z; As[1][kq*4+3][r] = u.w;
            }
        }
        // W tile(s): 16 k x 128 n = 512 float4, 2 per thread
        #pragma unroll
        for (int l = 0; l < 2; l++) {
            int e = tid + l*256;
            int n4 = e & 31, k = e >> 5;
            *(float4*)&Ws[0][k][n4*4] =
                *(const float4*)(jb.W + (size_t)(k0 + k)*N + n4*4);
            if (dual)
                *(float4*)&Ws[1][k][n4*4] =
                    *(const float4*)(jb.W2 + (size_t)(k0 + k)*N + n4*4);
        }
        __syncthreads();
        #pragma unroll
        for (int k = 0; k < BK; k++) {
            float a[8], w[8];
            *(float4*)&a[0] = *(const float4*)&As[0][k][ty*8];
            *(float4*)&a[4] = *(const float4*)&As[0][k][ty*8 + 4];
            *(float4*)&w[0] = *(const float4*)&Ws[0][k][tx*8];
            *(float4*)&w[4] = *(const float4*)&Ws[0][k][tx*8 + 4];
            #pragma unroll
            for (int j = 0; j < 8; j++)
                #pragma unroll
                for (int c = 0; c < 8; c++) acc[j][c] += a[j] * w[c];
            if (dual) {
                float a2[8], w2[8];
                *(float4*)&a2[0] = *(const float4*)&As[1][k][ty*8];
                *(float4*)&a2[4] = *(const float4*)&As[1][k][ty*8 + 4];
                *(float4*)&w2[0] = *(const float4*)&Ws[1][k][tx*8];
                *(float4*)&w2[4] = *(const float4*)&Ws[1][k][tx*8 + 4];
                #pragma unroll
                for (int j = 0; j < 8; j++)
                    #pragma unroll
                    for (int c = 0; c < 8; c++) acc[j][c] += a2[j] * w2[c];
            }
        }
        __syncthreads();
    }
    // epilogue
    float bv[8];
    if (jb.bias) {
        *(float4*)&bv[0] = *(const float4*)(jb.bias + tx*8);
        *(float4*)&bv[4] = *(const float4*)(jb.bias + tx*8 + 4);
    } else {
        #pragma unroll
        for (int c = 0; c < 8; c++) bv[c] = 0.0f;
    }
    #pragma unroll
    for (int j = 0; j < 8; j++) {
        int r = row0 + ty*8 + j;
        float o[8];
        #pragma unroll
        for (int c = 0; c < 8; c++) {
            float v = acc[j][c] + bv[c];
            o[c] = (ACT == 1) ? leaky(v) : v;
        }
        *(float4*)(jb.out + (size_t)r*N + tx*8)     = *(float4*)&o[0];
        *(float4*)(jb.out + (size_t)r*N + tx*8 + 4) = *(float4*)&o[4];
    }
}

// ---------------- kernel 3: causal scores ------------------------------------
// scores[b,i,j] = sum_h w0[h]*sigmoid(x1[j,b,h]+q[i,b,h]),  j<=i else 0
// One block per (b, 32x32 lower-triangular (i,j) tile): 64*10 = 640 blocks.
__global__ __launch_bounds__(256)
void scores_k(const float* __restrict__ x1, const float* __restrict__ q,
              const float* __restrict__ w0)
{
    int p = blockIdx.x % 10;
    int b = blockIdx.x / 10;
    int ti = 0;
    while ((ti + 1) * (ti + 2) / 2 <= p) ti++;
    int tj = p - ti * (ti + 1) / 2;
    const int i0 = ti * 32, j0 = tj * 32;

    __shared__ float qs[128][33];   // [h][i_local]
    __shared__ float xs[128][33];   // [h][j_local]
    __shared__ float w0s[128];

    int tid = threadIdx.x;
    if (tid < 128) w0s[tid] = w0[tid];
    #pragma unroll
    for (int l = 0; l < 16; l++) {
        int e = tid + l*256;
        int h = e & 127, r = e >> 7;        // r in [0,32)
        qs[h][r] = q [((i0 + r)*BB + b)*HH + h];
        xs[h][r] = x1[((j0 + r)*BB + b)*HH + h];
    }
    __syncthreads();

    int tx = tid & 15, ty = tid >> 4;
    int ia = ty * 2, ja = tx * 2;
    float a00 = 0.f, a01 = 0.f, a10 = 0.f, a11 = 0.f;
    #pragma unroll 4
    for (int h = 0; h < 128; h++) {
        float w  = w0s[h];
        float qa = qs[h][ia],  qb = qs[h][ia + 1];
        float xa = xs[h][ja],  xb = xs[h][ja + 1];
        a00 += w * sigf(qa + xa);
        a01 += w * sigf(qa + xb);
        a10 += w * sigf(qb + xa);
        a11 += w * sigf(qb + xb);
    }
    int i_0 = i0 + ia, i_1 = i_0 + 1;
    int j_0 = j0 + ja, j_1 = j_0 + 1;
    float* sp = g_sc + (size_t)b * TT * TT;
    sp[i_0*TT + j_0] = (j_0 <= i_0) ? a00 : 0.0f;
    sp[i_0*TT + j_1] = (j_1 <= i_0) ? a01 : 0.0f;
    sp[i_1*TT + j_0] = (j_0 <= i_1) ? a10 : 0.0f;
    sp[i_1*TT + j_1] = (j_1 <= i_1) ? a11 : 0.0f;
}

// ---------------- kernel 4: m_a[i,b,h] = sum_{j<=i} scores[b,i,j]*inputs[j,b,h]
// One block per (b, 32-row i tile): 64*4 = 256 blocks.
__global__ __launch_bounds__(256)
void ma_k(const float* __restrict__ inputs)
{
    int it = blockIdx.x & 3;
    int b  = blockIdx.x >> 2;
    int i0 = it * 32;

    __shared__ float ins[32][128];
    __shared__ float ss [32][33];

    int tid = threadIdx.x;
    int tx = tid & 15, ty = tid >> 4;   // h = c*16+tx (8 each); i = ty*2+d
    float acc[2][8];
    #pragma unroll
    for (int d = 0; d < 2; d++)
        #pragma unroll
        for (int c = 0; c < 8; c++) acc[d][c] = 0.0f;

    for (int jt = 0; jt <= it; jt++) {
        int j0 = jt * 32;
        #pragma unroll
        for (int l = 0; l < 16; l++) {
            int e = tid + l*256;
            int h = e & 127, r = e >> 7;
            ins[r][h] = inputs[((j0 + r)*BB + b)*HH + h];
        }
        #pragma unroll
        for (int l = 0; l < 4; l++) {
            int e = tid + l*256;
            int jj = e & 31, ii = e >> 5;
            ss[ii][jj] = g_sc[((size_t)b*TT + i0 + ii)*TT + j0 + jj];
        }
        __syncthreads();
        #pragma unroll 4
        for (int jj = 0; jj < 32; jj++) {
            float s0 = ss[ty*2][jj], s1 = ss[ty*2 + 1][jj];
            #pragma unroll
            for (int c = 0; c < 8; c++) {
                float v = ins[jj][c*16 + tx];
                acc[0][c] += s0 * v;
                acc[1][c] += s1 * v;
            }
        }
        __syncthreads();
    }
    #pragma unroll
    for (int d = 0; d < 2; d++) {
        int i = i0 + ty*2 + d;
        #pragma unroll
        for (int c = 0; c < 8; c++)
            g_ma[((size_t)i*BB + b)*HH + c*16 + tx] = acc[d][c];
    }
}

// ---------------- fused layer-1 (pc & pv) + dot + sigmoid + product ----------
// Per block: 64 rows. Four GEMMs [64x128]@[128x64] (a1c,b1c,a1v,b1v) kept in
// registers, leaky, per-row dots, sigmoid; out_c and out_v = sig_v*sig_c.
__global__ __launch_bounds__(256)
void l1dot_k(const float* __restrict__ a0c, const float* __restrict__ b0c,
             const float* __restrict__ a0v, const float* __restrict__ b0v,
             const float* __restrict__ wac, const float* __restrict__ bac,
             const float* __restrict__ wbc, const float* __restrict__ bbc,
             const float* __restrict__ wav, const float* __restrict__ bav,
             const float* __restrict__ wbv, const float* __restrict__ bbv,
             float* __restrict__ out)
{
    constexpr int BM = 64, BK = 16, K = 128, N = 64;
    __shared__ float As[4][BK][BM + 4];   // 17.4 KB
    __shared__ float Ws[4][BK][N];        // 16.4 KB

    const float* Ap[4] = {a0c, b0c, a0v, b0v};
    const float* Wp[4] = {wac, wbc, wav, wbv};

    const int tid = threadIdx.x;
    const int tx = tid & 15;              // cols tx*4 .. tx*4+3
    const int ty = tid >> 4;              // rows ty*4 .. ty*4+3
    const int row0 = blockIdx.x * BM;

    float acc[4][4][4];                   // [tensor][row][col]
    #pragma unroll
    for (int t = 0; t < 4; t++)
        #pragma unroll
        for (int j = 0; j < 4; j++)
            #pragma unroll
            for (int c = 0; c < 4; c++) acc[t][j][c] = 0.0f;

    for (int k0 = 0; k0 < K; k0 += BK) {
        // A tiles: per t, 64 rows x 16 k = 256 float4 = 1 per thread
        int kq = tid & 3, r = tid >> 2;
        int n4 = tid & 15, kk = tid >> 4;
        #pragma unroll
        for (int t = 0; t < 4; t++) {
            float4 v = *(const float4*)(Ap[t] + (size_t)(row0 + r)*K + k0 + kq*4);
            As[t][kq*4+0][r] = v.x; As[t][kq*4+1][r] = v.y;
            As[t][kq*4+2][r] = v.z; As[t][kq*4+3][r] = v.w;
            *(float4*)&Ws[t][kk][n4*4] =
                *(const float4*)(Wp[t] + (size_t)(k0 + kk)*N + n4*4);
        }
        __syncthreads();
        #pragma unroll
        for (int k = 0; k < BK; k++) {
            #pragma unroll
            for (int t = 0; t < 4; t++) {
                float a[4], w[4];
                *(float4*)&a[0] = *(const float4*)&As[t][k][ty*4];
                *(float4*)&w[0] = *(const float4*)&Ws[t][k][tx*4];
                #pragma unroll
                for (int j = 0; j < 4; j++)
                    #pragma unroll
                    for (int c = 0; c < 4; c++) acc[t][j][c] += a[j] * w[c];
            }
        }
        __syncthreads();
    }

    // biases for this thread's 4 cols
    float vac[4], vbc[4], vav[4], vbv[4];
    *(float4*)&vac[0] = *(const float4*)(bac + tx*4);
    *(float4*)&vbc[0] = *(const float4*)(bbc + tx*4);
    *(float4*)&vav[0] = *(const float4*)(bav + tx*4);
    *(float4*)&vbv[0] = *(const float4*)(bbv + tx*4);

    float dc[4], dv[4];
    #pragma unroll
    for (int j = 0; j < 4; j++) {
        dc[j] = 0.0f; dv[j] = 0.0f;
        #pragma unroll
        for (int c = 0; c < 4; c++) {
            dc[j] += leaky(acc[0][j][c] + vac[c]) * leaky(acc[1][j][c] + vbc[c]);
            dv[j] += leaky(acc[2][j][c] + vav[c]) * leaky(acc[3][j][c] + vbv[c]);
        }
    }
    // reduce across the 16 tx lanes (xor <=8 stays within each 16-lane group)
    #pragma unroll
    for (int m = 8; m >= 1; m >>= 1)
        #pragma unroll
        for (int j = 0; j < 4; j++) {
            dc[j] += __shfl_xor_sync(0xffffffffu, dc[j], m);
            dv[j] += __shfl_xor_sync(0xffffffffu, dv[j], m);
        }

    if (tx == 0) {
        #pragma unroll
        for (int j = 0; j < 4; j++) {
            int r = row0 + ty*4 + j;
            float pc = sigf(dc[j]);
            out[r]      = pc;
            out[MM + r] = sigf(dv[j]) * pc;
        }
    }
}

// ---------------- launch -----------------------------------------------------
extern "C" void kernel_launch(void* const* d_in, const int* in_sizes, int n_in,
                              void* d_out, int out_size)
{
    const float* inputs = (const float*)d_in[0];
    const float* w1_k   = (const float*)d_in[1];
    const float* w1_b   = (const float*)d_in[2];
    const float* w2_k   = (const float*)d_in[3];
    const float* w3_k   = (const float*)d_in[4];
    const float* w0_k   = (const float*)d_in[5];
    const float* pc0a_k = (const float*)d_in[6];
    const float* pc0a_b = (const float*)d_in[7];
    const float* pc0b_k = (const float*)d_in[8];
    const float* pc0b_b = (const float*)d_in[9];
    const float* pc1a_k = (const float*)d_in[10];
    const float* pc1a_b = (const float*)d_in[11];
    const float* pc1b_k = (const float*)d_in[12];
    const float* pc1b_b = (const float*)d_in[13];
    const float* pv0a_k = (const float*)d_in[14];
    const float* pv0a_b = (const float*)d_in[15];
    const float* pv0b_k = (const float*)d_in[16];
    const float* pv0b_b = (const float*)d_in[17];
    const float* pv1a_k = (const float*)d_in[18];
    const float* pv1a_b = (const float*)d_in[19];
    const float* pv1b_k = (const float*)d_in[20];
    const float* pv1b_b = (const float*)d_in[21];

    float *ms, *x1, *q, *ma, *a0c, *b0c, *a0v, *b0v;
    cudaGetSymbolAddress((void**)&ms,  g_ms);
    cudaGetSymbolAddress((void**)&x1,  g_x1);
    cudaGetSymbolAddress((void**)&q,   g_q);
    cudaGetSymbolAddress((void**)&ma,  g_ma);
    cudaGetSymbolAddress((void**)&a0c, g_a0c);
    cudaGetSymbolAddress((void**)&b0c, g_b0c);
    cudaGetSymbolAddress((void**)&a0v, g_a0v);
    cudaGetSymbolAddress((void**)&b0v, g_b0v);

    float* out = (float*)d_out;   // [0..MM): prediction_c, [MM..2MM): prediction_v

    // 1) running mean
    cumsum_k<<<(BB*HH + 255)/256, 256>>>(inputs);

    // 2) x1 = inputs@w1 + b ;  q = inputs@w2 + m_s@w3   (one launch, y=2)
    GJobs jq = {};
    jq.j[0] = { inputs, w1_k, w1_b,   nullptr, nullptr, x1 };
    jq.j[1] = { inputs, w2_k, nullptr, ms,     w3_k,    q  };
    gemm128_k<0><<<dim3(MM/128, 2), 256>>>(jq);

    // 3) causal scores (triangular tiles only)
    scores_k<<<64*10, 256>>>(x1, q, w0_k);

    // 4) m_a
    ma_k<<<BB*4, 256>>>(inputs);

    // 5) all four layer-0 GEMMs in one launch (leaky activation)
    GJobs j0 = {};
    j0.j[0] = { ma,     pc0a_k, pc0a_b, nullptr, nullptr, a0c };
    j0.j[1] = { inputs, pc0b_k, pc0b_b, nullptr, nullptr, b0c };
    j0.j[2] = { ma,     pv0a_k, pv0a_b, nullptr, nullptr, a0v };
    j0.j[3] = { inputs, pv0b_k, pv0b_b, nullptr, nullptr, b0v };
    gemm128_k<1><<<dim3(MM/128, 4), 256>>>(j0);

    // 6) fused layer-1 + dot + sigmoid + pv*=pc
    l1dot_k<<<MM/64, 256>>>(a0c, b0c, a0v, b0v,
                            pc1a_k, pc1a_b, pc1b_k, pc1b_b,
                            pv1a_k, pv1a_b, pv1b_k, pv1b_b, out);
}